// round 9
// baseline (speedup 1.0000x reference)
#include <cuda_runtime.h>
#include <cstdint>
#include <cstddef>

// Problem constants
#define Bsz 16
#define Ssz 512
#define Nent 64
#define Hdim 768
#define HH 384          // H/2
#define ET 9
#define RT 10
#define NPAIR 2016      // 64*63/2
#define MS (Bsz*Ssz)    // 8192
#define ME (Bsz*Nent)   // 1024
#define PAIRN (2*Hdim)  // 1536
#define ZPAIR 4         // split-K factor, pair GEMM

// Scratch (static device arrays — allocation-free rule)
__device__ float g_hidden[(size_t)MS * HH];            // relu(seq@W1e+b1e)
__device__ float g_pK[ZPAIR][(size_t)ME * PAIRN];      // pair GEMM split-K partials
__device__ float g_pAT[(size_t)Bsz * Hdim * Nent];     // pA+b1r transposed [b][k][n]
__device__ float g_pBT[(size_t)Bsz * Hdim * Nent];     // pB transposed [b][k][n]
__device__ int   g_pairs[2048 * 2];                    // pair index table

// ===========================================================================
// Packed fp32x2 + cp.async helpers (base-ISA PTX)
// ===========================================================================
__device__ __forceinline__ void ffma2(unsigned long long& d,
                                      unsigned long long a,
                                      unsigned long long b) {
    asm("fma.rn.f32x2 %0, %1, %2, %0;" : "+l"(d) : "l"(a), "l"(b));
}
__device__ __forceinline__ unsigned long long dup2(float x) {
    unsigned long long r; unsigned u = __float_as_uint(x);
    asm("mov.b64 %0, {%1, %1};" : "=l"(r) : "r"(u));
    return r;
}
__device__ __forceinline__ float2 unpack2(unsigned long long v) {
    unsigned lo, hi;
    asm("mov.b64 {%0, %1}, %2;" : "=r"(lo), "=r"(hi) : "l"(v));
    return make_float2(__uint_as_float(lo), __uint_as_float(hi));
}
__device__ __forceinline__ uint32_t smem_u32(const void* p) {
    uint32_t a;
    asm("{ .reg .u64 t; cvta.to.shared.u64 t, %1; cvt.u32.u64 %0, t; }"
        : "=r"(a) : "l"(p));
    return a;
}
__device__ __forceinline__ void cp_async16(uint32_t saddr, const void* gaddr) {
    asm volatile("cp.async.cg.shared.global [%0], [%1], 16;"
                 :: "r"(saddr), "l"(gaddr) : "memory");
}
#define CP_COMMIT() asm volatile("cp.async.commit_group;" ::: "memory")
#define CP_WAIT0()  asm volatile("cp.async.wait_group 0;" ::: "memory")

// ===========================================================================
// Merged FFMA2 SGEMM megakernel (verified R8 win; two classes, one grid):
//   class E (bid%3==0): hidden = relu(seq[8192,768] @ W1e[768,384] + b1e)
//       384 CTAs: nx in 0..2, my in 0..127, K=768 (24 chunks)
//   class P (else):     pK[z] = ER[1024,768] @ [W1r_top|W1r_bot] (z-th K slice)
//       768 CTAs: z in 0..3, nx in 0..11, my in 0..15, Kper=192 (6 chunks)
// CTA tile 64x128, BK=32, 128 threads, microtile rows {4lm+j}∪{32+4lm+j} x 8.
// A LDG->STS transposed+swizzled; B streams via cp.async.
// ===========================================================================
#define GTM 64
#define GTN 128
#define GTK 32
#define ASTRIDE 68                     // words per k-row of A smem
#define ASTAGE (GTK*ASTRIDE)           // 2176 floats
#define BSTAGE (GTK*GTN)               // 4096 floats
#define GEMM_SMEM ((2*ASTAGE + 2*BSTAGE) * 4)   // 50176 bytes

__global__ __launch_bounds__(128) void gemm_mega(
    const float* __restrict__ seq,  const float* __restrict__ W1e,
    const float* __restrict__ b1e,  float* __restrict__ hidden,
    const float* __restrict__ ER,   const float* __restrict__ W1r,
    float* __restrict__ pK)
{
    extern __shared__ float sm[];
    float* smA = sm;                   // 2 stages x ASTAGE
    float* smB = sm + 2 * ASTAGE;      // 2 stages x BSTAGE

    const int tid = threadIdx.x;
    const int wid = tid >> 5, lane = tid & 31;
    const int lm = lane >> 2;          // 0..7
    const int ln = lane & 3;           // 0..3
    const int col0 = wid * 32 + ln * 8;

    // ---- class dispatch ----
    const int bid = blockIdx.x;
    const bool isEnt = (bid % 3) == 0;

    const float* Ab;  int lda;
    const float* Bb;  int ldb;
    float* Cb;        int ldc;
    int CH, bm, colg0;

    if (isEnt) {
        int id = bid / 3;              // 0..383
        int nx = id % 3, my = id / 3;
        bm = my * GTM; colg0 = nx * GTN;
        lda = Hdim; ldb = HH; ldc = HH;
        Ab = seq + (size_t)bm * lda;
        Bb = W1e + colg0;
        Cb = hidden;
        CH = Hdim / GTK;               // 24
    } else {
        int id = bid - 1 - (bid - 1) / 3;   // 0..767
        int z = id / 192;
        int rem = id % 192;
        int nx = rem % 12, my = rem / 12;
        bm = my * GTM; colg0 = nx * GTN;
        lda = Hdim; ldb = Hdim; ldc = PAIRN;
        const int Kper = Hdim / ZPAIR;      // 192
        Ab = ER + (size_t)z * Kper + (size_t)bm * lda;
        int bn = colg0;
        const float* Bsel = W1r;
        if (bn >= Hdim) { Bsel = W1r + (size_t)Hdim * Hdim; bn -= Hdim; }
        Bb = Bsel + (size_t)z * Kper * ldb + bn;
        Cb = pK + (size_t)z * ((size_t)ME * PAIRN);
        CH = Kper / GTK;               // 6
    }

    unsigned long long acc[4][8];      // [row-pair][col]
#pragma unroll
    for (int r = 0; r < 4; r++)
#pragma unroll
        for (int c = 0; c < 8; c++) acc[r][c] = 0ull;

    float4 ra[4];

    // A: 64x32 tile = 512 float4; idx=q*128+tid -> m=idx>>3, kq=(idx&7)*4
#define LDG_A(k0) do { \
    _Pragma("unroll") \
    for (int q = 0; q < 4; q++) { \
        int idx = q * 128 + tid; \
        int m = idx >> 3, kq = (idx & 7) << 2; \
        ra[q] = *(const float4*)(Ab + (size_t)m * lda + (k0) + kq); \
    } \
} while (0)
    // STS transposed + swizzle: addr(k,m) = k*68 + (m ^ (k & 28))
#define STS_A(dst) do { \
    _Pragma("unroll") \
    for (int q = 0; q < 4; q++) { \
        int idx = q * 128 + tid; \
        int m = idx >> 3, kq = (idx & 7) << 2; \
        int ms = m ^ kq; \
        (dst)[(kq + 0) * ASTRIDE + ms] = ra[q].x; \
        (dst)[(kq + 1) * ASTRIDE + ms] = ra[q].y; \
        (dst)[(kq + 2) * ASTRIDE + ms] = ra[q].z; \
        (dst)[(kq + 3) * ASTRIDE + ms] = ra[q].w; \
    } \
} while (0)
    // B: 32x128 tile = 1024 float4; idx=q*128+tid -> k=idx>>5, c4=(idx&31)*4
#define CPA_B(k0, stB) do { \
    uint32_t sb = smem_u32(smB + (stB) * BSTAGE) + (uint32_t)tid * 16u; \
    _Pragma("unroll") \
    for (int q = 0; q < 8; q++) { \
        int idx = q * 128 + tid; \
        int k = idx >> 5, c4 = (idx & 31) << 2; \
        cp_async16(sb + q * 2048u, Bb + (size_t)((k0) + k) * ldb + c4); \
    } \
    CP_COMMIT(); \
} while (0)

    // ---- prologue ----
    CPA_B(0, 0);
    LDG_A(0);
    STS_A(smA);
    CP_WAIT0();
    __syncthreads();

    for (int c = 0; c < CH; c++) {
        const int st = c & 1;
        const int nx2 = st ^ 1;
        if (c + 1 < CH) {
            CPA_B((c + 1) * GTK, nx2);
            LDG_A((c + 1) * GTK);
        }

        const float* Asm = smA + st * ASTAGE;
        const float* Bsm = smB + st * BSTAGE;
#pragma unroll
        for (int k = 0; k < GTK; k++) {
            const int sw = k & 28;
            ulonglong2 ap0 = *(const ulonglong2*)&Asm[k * ASTRIDE + ((4 * lm) ^ sw)];
            ulonglong2 ap1 = *(const ulonglong2*)&Asm[k * ASTRIDE + (32 + ((4 * lm) ^ sw))];
            float4 b0 = *(const float4*)&Bsm[k * GTN + col0];
            float4 b1 = *(const float4*)&Bsm[k * GTN + col0 + 4];
            unsigned long long bd[8];
            bd[0] = dup2(b0.x); bd[1] = dup2(b0.y); bd[2] = dup2(b0.z); bd[3] = dup2(b0.w);
            bd[4] = dup2(b1.x); bd[5] = dup2(b1.y); bd[6] = dup2(b1.z); bd[7] = dup2(b1.w);
            unsigned long long ap[4] = {ap0.x, ap0.y, ap1.x, ap1.y};
#pragma unroll
            for (int r = 0; r < 4; r++)
#pragma unroll
                for (int cc = 0; cc < 8; cc++)
                    ffma2(acc[r][cc], ap[r], bd[cc]);
        }

        if (c + 1 < CH) STS_A(smA + nx2 * ASTAGE);
        CP_WAIT0();
        __syncthreads();
    }

    // ---- epilogue ----
    const int colg = colg0 + col0;
    float bb[8] = {0, 0, 0, 0, 0, 0, 0, 0};
    if (isEnt) {
        float4 t0 = *(const float4*)(b1e + colg);
        float4 t1 = *(const float4*)(b1e + colg + 4);
        bb[0] = t0.x; bb[1] = t0.y; bb[2] = t0.z; bb[3] = t0.w;
        bb[4] = t1.x; bb[5] = t1.y; bb[6] = t1.z; bb[7] = t1.w;
    }
#pragma unroll
    for (int rp = 0; rp < 4; rp++) {
        int r0 = (rp < 2) ? (4 * lm + 2 * rp) : (32 + 4 * lm + 2 * (rp - 2));
        float lo[8], hi[8];
#pragma unroll
        for (int cc = 0; cc < 8; cc++) {
            float2 v = unpack2(acc[rp][cc]);
            lo[cc] = v.x + bb[cc];
            hi[cc] = v.y + bb[cc];
        }
        if (isEnt) {
#pragma unroll
            for (int q = 0; q < 8; q++) {
                lo[q] = fmaxf(lo[q], 0.f);
                hi[q] = fmaxf(hi[q], 0.f);
            }
        }
        float* C0 = Cb + (size_t)(bm + r0) * ldc + colg;
        float* C1 = Cb + (size_t)(bm + r0 + 1) * ldc + colg;
        *(float4*)C0 = make_float4(lo[0], lo[1], lo[2], lo[3]);
        *(float4*)(C0 + 4) = make_float4(lo[4], lo[5], lo[6], lo[7]);
        *(float4*)C1 = make_float4(hi[0], hi[1], hi[2], hi[3]);
        *(float4*)(C1 + 4) = make_float4(hi[4], hi[5], hi[6], hi[7]);
    }
#undef LDG_A
#undef STS_A
#undef CPA_B
}

// ===========================================================================
// Merged launch 3: EL | combine_transpose | pair-table build.
//  EL (bid < ELBLKS): entity_logits = hidden @ W2e + b2e, warp per row.
//  combine (ELBLKS <= bid < ELBLKS+CTBLKS): pAT/pBT = transpose(sum pK + bias)
//  pairs (else, 8 blocks): g_pairs[p] = (i, j) triu(k=1) ordering.
// ===========================================================================
#define ELBLKS (MS / 8)                      // 1024
#define CTBLKS ((PAIRN / 32) * (ME / 32))    // 1536
#define PTBLKS 8                             // 8*256 = 2048 >= NPAIR

__global__ __launch_bounds__(256) void el_combine_kernel(
    const float* __restrict__ W2e, const float* __restrict__ b2e,
    const float* __restrict__ b1r, float* __restrict__ el_out)
{
    __shared__ float W2s[HH * ET];           // EL use (13.8 KB)
    __shared__ float t[32][33];              // combine use (4.3 KB)
    const int tid = threadIdx.x;

    if (blockIdx.x < ELBLKS) {
        // ---------------- entity logits ----------------
        for (int i = tid; i < HH * ET; i += 256) W2s[i] = W2e[i];
        __syncthreads();

        const int warp = tid >> 5, lane = tid & 31;
        const int row = blockIdx.x * 8 + warp;
        const float* hrow = g_hidden + (size_t)row * HH;

        float acc[ET];
#pragma unroll
        for (int c = 0; c < ET; c++) acc[c] = 0.f;

#pragma unroll
        for (int kk = 0; kk < HH / 32; kk++) {
            int k = kk * 32 + lane;
            float h = hrow[k];
            const float* w = &W2s[k * ET];
#pragma unroll
            for (int c = 0; c < ET; c++) acc[c] += h * w[c];
        }
#pragma unroll
        for (int c = 0; c < ET; c++)
#pragma unroll
            for (int off = 16; off > 0; off >>= 1)
                acc[c] += __shfl_down_sync(0xffffffffu, acc[c], off);

        if (lane == 0) {
            float* o = el_out + (size_t)row * ET;
#pragma unroll
            for (int c = 0; c < ET; c++) o[c] = acc[c] + b2e[c];
        }
    } else if (blockIdx.x < ELBLKS + CTBLKS) {
        // ---------------- combine + transpose ----------------
        const int cb = blockIdx.x - ELBLKS;          // 0..1535
        const int kb = (cb % (PAIRN / 32)) * 32;     // k' base
        const int eb = (cb / (PAIRN / 32)) * 32;     // entity-row base
        const int tx = tid & 31;
        const int ty = tid >> 5;                      // 0..7

#pragma unroll
        for (int s = 0; s < 4; s++) {
            int e = eb + ty + s * 8;
            size_t off = (size_t)e * PAIRN + kb + tx;
            float v = g_pK[0][off];
#pragma unroll
            for (int zz = 1; zz < ZPAIR; zz++) v += g_pK[zz][off];
            t[ty + s * 8][tx] = v;
        }
        __syncthreads();

        const int b = eb >> 6;
        const int n0 = eb & 63;
#pragma unroll
        for (int s = 0; s < 4; s++) {
            int kk = kb + ty + s * 8;
            float v = t[tx][ty + s * 8];
            if (kk < Hdim) {
                v += b1r[kk];
                g_pAT[((size_t)b * Hdim + kk) * Nent + n0 + tx] = v;
            } else {
                g_pBT[((size_t)b * Hdim + (kk - Hdim)) * Nent + n0 + tx] = v;
            }
        }
    } else {
        // ---------------- pair index table ----------------
        int p = (blockIdx.x - ELBLKS - CTBLKS) * 256 + tid;
        if (p < NPAIR) {
            int rem = p, i = 0;
            while (rem >= (Nent - 1) - i) { rem -= (Nent - 1) - i; i++; }
            g_pairs[p * 2]     = i;
            g_pairs[p * 2 + 1] = i + 1 + rem;
        }
    }
}

// ===========================================================================
// Span mean pooling, fixed 16-iteration predicated loop.
// ===========================================================================
__global__ __launch_bounds__(192) void span_pool_kernel(
    const float4* __restrict__ seq4, const int* __restrict__ spans,
    float4* __restrict__ er4)
{
    const int bn = blockIdx.x;
    const int b = bn >> 6;
    const int s0 = spans[bn * 2];
    const int s1 = spans[bn * 2 + 1];
    int cnt = s1 - s0; if (cnt < 1) cnt = 1;
    const float inv = 1.f / (float)cnt;
    const float4* base = seq4 + (size_t)b * Ssz * (Hdim / 4) + threadIdx.x;

    float4 acc = make_float4(0.f, 0.f, 0.f, 0.f);
#pragma unroll
    for (int q = 0; q < 16; q++) {
        int s = s0 + q;
        float4 v = base[(size_t)s * (Hdim / 4)];
        if (s < s1) { acc.x += v.x; acc.y += v.y; acc.z += v.z; acc.w += v.w; }
    }
    acc.x *= inv; acc.y *= inv; acc.z *= inv; acc.w *= inv;
    er4[(size_t)bn * (Hdim / 4) + threadIdx.x] = acc;
}

// ===========================================================================
// relation_logits: thread per pair (g_pairs table), W2 broadcast from smem,
// FFMA2 accumulators. 128-thread blocks, 256 CTAs (covers all SMs).
// h(k) = relu(pAT[b][k][i] + pBT[b][k][j]);  logits = h @ W2r + b2r
// ===========================================================================
__global__ __launch_bounds__(128) void relation_kernel(
    const float* __restrict__ W2r, const float* __restrict__ b2r,
    float* __restrict__ out)
{
    __shared__ __align__(16) float Wp[Hdim * 12];      // [k][12] padded
    const int tid = threadIdx.x;
    for (int idx = tid; idx < Hdim * 12; idx += 128) {
        int k = idx / 12, c = idx % 12;
        Wp[idx] = (c < RT) ? W2r[k * RT + c] : 0.f;
    }
    __syncthreads();

    const int b = blockIdx.y;
    const int p = blockIdx.x * 128 + tid;
    const bool act = (p < NPAIR);
    const int pc = act ? p : 0;
    const int i = g_pairs[pc * 2];
    const int j = g_pairs[pc * 2 + 1];

    const float* At = g_pAT + (size_t)b * Hdim * Nent;
    const float* Bt = g_pBT + (size_t)b * Hdim * Nent;

    unsigned long long acc[6];
#pragma unroll
    for (int c = 0; c < 6; c++) acc[c] = 0ull;

#pragma unroll 4
    for (int k = 0; k < Hdim; k++) {
        float h = fmaxf(At[(size_t)k * Nent + i] + Bt[(size_t)k * Nent + j], 0.f);
        unsigned long long hd = dup2(h);
        const ulonglong2* w = (const ulonglong2*)&Wp[k * 12];
        ulonglong2 w0 = w[0], w1 = w[1], w2 = w[2];
        ffma2(acc[0], hd, w0.x); ffma2(acc[1], hd, w0.y);
        ffma2(acc[2], hd, w1.x); ffma2(acc[3], hd, w1.y);
        ffma2(acc[4], hd, w2.x); ffma2(acc[5], hd, w2.y);
    }

    if (act) {
        float o[12];
#pragma unroll
        for (int c = 0; c < 6; c++) {
            float2 v = unpack2(acc[c]);
            o[c * 2] = v.x; o[c * 2 + 1] = v.y;
        }
        float* dst = out + (size_t)(b * NPAIR + p) * RT;
#pragma unroll
        for (int c = 0; c < RT; c++) dst[c] = o[c] + b2r[c];
    }
}

// ===========================================================================
extern "C" void kernel_launch(void* const* d_in, const int* in_sizes, int n_in,
                              void* d_out, int out_size)
{
    const float* seq   = (const float*)d_in[0];
    const int*   spans = (const int*)d_in[2];
    const float* W1e   = (const float*)d_in[3];
    const float* b1e   = (const float*)d_in[4];
    const float* W2e   = (const float*)d_in[5];
    const float* b2e   = (const float*)d_in[6];
    const float* W1r   = (const float*)d_in[7];
    const float* b1r   = (const float*)d_in[8];
    const float* W2r   = (const float*)d_in[9];
    const float* b2r   = (const float*)d_in[10];

    float* out = (float*)d_out;
    float* EL = out;                                   // [16,512,9]
    float* ER = out + (size_t)MS * ET;                 // [16,64,768]
    float* RL = ER + (size_t)ME * Hdim;                // [16,2016,10]

    void *p_hidden, *p_pK;
    cudaGetSymbolAddress(&p_hidden, g_hidden);
    cudaGetSymbolAddress(&p_pK, g_pK);

    cudaFuncSetAttribute(gemm_mega,
                         cudaFuncAttributeMaxDynamicSharedMemorySize, GEMM_SMEM);

    // 1) entity_repr (output + input of pair GEMM)
    span_pool_kernel<<<Bsz * Nent, 192>>>((const float4*)seq, spans, (float4*)ER);

    // 2) merged GEMMs: hidden (entity) + pK[z] (pair split-K=4), 1152 CTAs
    gemm_mega<<<1152, 128, GEMM_SMEM>>>(
        seq, W1e, b1e, (float*)p_hidden, ER, W1r, (float*)p_pK);

    // 3) entity_logits | combine+transpose | pair table
    el_combine_kernel<<<ELBLKS + CTBLKS + PTBLKS, 256>>>(W2e, b2e, b1r, EL);

    // 4) relation_logits
    relation_kernel<<<dim3((NPAIR + 127) / 128, Bsz), 128>>>(W2r, b2r, RL);
}

// round 10
// speedup vs baseline: 1.1498x; 1.1498x over previous
#include <cuda_runtime.h>
#include <cstdint>
#include <cstddef>

// Problem constants
#define Bsz 16
#define Ssz 512
#define Nent 64
#define Hdim 768
#define HH 384          // H/2
#define ET 9
#define RT 10
#define NPAIR 2016      // 64*63/2
#define MS (Bsz*Ssz)    // 8192
#define ME (Bsz*Nent)   // 1024
#define PAIRN (2*Hdim)  // 1536
#define ZPAIR 4         // split-K factor, pair GEMM

// Scratch (static device arrays — allocation-free rule)
__device__ float g_hidden[(size_t)MS * HH];            // relu(seq@W1e+b1e)
__device__ float g_pK[ZPAIR][(size_t)ME * PAIRN];      // pair GEMM split-K partials
__device__ float g_pAT[(size_t)Bsz * Hdim * Nent];     // pA+b1r transposed [b][k][n]
__device__ float g_pBT[(size_t)Bsz * Hdim * Nent];     // pB transposed [b][k][n]
__device__ float g_Wp12[(size_t)Hdim * 12];            // W2r padded to 12 cols
__device__ int   g_pairs[2048 * 2];                    // pair index table

// ===========================================================================
// Packed fp32x2 + cp.async helpers (base-ISA PTX)
// ===========================================================================
__device__ __forceinline__ void ffma2(unsigned long long& d,
                                      unsigned long long a,
                                      unsigned long long b) {
    asm("fma.rn.f32x2 %0, %1, %2, %0;" : "+l"(d) : "l"(a), "l"(b));
}
__device__ __forceinline__ unsigned long long dup2(float x) {
    unsigned long long r; unsigned u = __float_as_uint(x);
    asm("mov.b64 %0, {%1, %1};" : "=l"(r) : "r"(u));
    return r;
}
__device__ __forceinline__ float2 unpack2(unsigned long long v) {
    unsigned lo, hi;
    asm("mov.b64 {%0, %1}, %2;" : "=r"(lo), "=r"(hi) : "l"(v));
    return make_float2(__uint_as_float(lo), __uint_as_float(hi));
}
__device__ __forceinline__ uint32_t smem_u32(const void* p) {
    uint32_t a;
    asm("{ .reg .u64 t; cvta.to.shared.u64 t, %1; cvt.u32.u64 %0, t; }"
        : "=r"(a) : "l"(p));
    return a;
}
__device__ __forceinline__ void cp_async16(uint32_t saddr, const void* gaddr) {
    asm volatile("cp.async.cg.shared.global [%0], [%1], 16;"
                 :: "r"(saddr), "l"(gaddr) : "memory");
}
#define CP_COMMIT() asm volatile("cp.async.commit_group;" ::: "memory")
#define CP_WAIT0()  asm volatile("cp.async.wait_group 0;" ::: "memory")

// ===========================================================================
// Merged FFMA2 SGEMM megakernel (verified R8 win; two classes, one grid):
//   class E (bid%3==0): hidden = relu(seq[8192,768] @ W1e[768,384] + b1e)
//   class P (else):     pK[z] = ER[1024,768] @ [W1r_top|W1r_bot] (z-th K slice)
// CTA tile 64x128, BK=32, 128 threads, microtile rows {4lm+j}∪{32+4lm+j} x 8.
// ===========================================================================
#define GTM 64
#define GTN 128
#define GTK 32
#define ASTRIDE 68                     // words per k-row of A smem
#define ASTAGE (GTK*ASTRIDE)           // 2176 floats
#define BSTAGE (GTK*GTN)               // 4096 floats
#define GEMM_SMEM ((2*ASTAGE + 2*BSTAGE) * 4)   // 50176 bytes

__global__ __launch_bounds__(128) void gemm_mega(
    const float* __restrict__ seq,  const float* __restrict__ W1e,
    const float* __restrict__ b1e,  float* __restrict__ hidden,
    const float* __restrict__ ER,   const float* __restrict__ W1r,
    float* __restrict__ pK)
{
    extern __shared__ float sm[];
    float* smA = sm;                   // 2 stages x ASTAGE
    float* smB = sm + 2 * ASTAGE;      // 2 stages x BSTAGE

    const int tid = threadIdx.x;
    const int wid = tid >> 5, lane = tid & 31;
    const int lm = lane >> 2;          // 0..7
    const int ln = lane & 3;           // 0..3
    const int col0 = wid * 32 + ln * 8;

    // ---- class dispatch ----
    const int bid = blockIdx.x;
    const bool isEnt = (bid % 3) == 0;

    const float* Ab;  int lda;
    const float* Bb;  int ldb;
    float* Cb;        int ldc;
    int CH, bm, colg0;

    if (isEnt) {
        int id = bid / 3;              // 0..383
        int nx = id % 3, my = id / 3;
        bm = my * GTM; colg0 = nx * GTN;
        lda = Hdim; ldb = HH; ldc = HH;
        Ab = seq + (size_t)bm * lda;
        Bb = W1e + colg0;
        Cb = hidden;
        CH = Hdim / GTK;               // 24
    } else {
        int id = bid - 1 - (bid - 1) / 3;   // 0..767
        int z = id / 192;
        int rem = id % 192;
        int nx = rem % 12, my = rem / 12;
        bm = my * GTM; colg0 = nx * GTN;
        lda = Hdim; ldb = Hdim; ldc = PAIRN;
        const int Kper = Hdim / ZPAIR;      // 192
        Ab = ER + (size_t)z * Kper + (size_t)bm * lda;
        int bn = colg0;
        const float* Bsel = W1r;
        if (bn >= Hdim) { Bsel = W1r + (size_t)Hdim * Hdim; bn -= Hdim; }
        Bb = Bsel + (size_t)z * Kper * ldb + bn;
        Cb = pK + (size_t)z * ((size_t)ME * PAIRN);
        CH = Kper / GTK;               // 6
    }

    unsigned long long acc[4][8];      // [row-pair][col]
#pragma unroll
    for (int r = 0; r < 4; r++)
#pragma unroll
        for (int c = 0; c < 8; c++) acc[r][c] = 0ull;

    float4 ra[4];

#define LDG_A(k0) do { \
    _Pragma("unroll") \
    for (int q = 0; q < 4; q++) { \
        int idx = q * 128 + tid; \
        int m = idx >> 3, kq = (idx & 7) << 2; \
        ra[q] = *(const float4*)(Ab + (size_t)m * lda + (k0) + kq); \
    } \
} while (0)
#define STS_A(dst) do { \
    _Pragma("unroll") \
    for (int q = 0; q < 4; q++) { \
        int idx = q * 128 + tid; \
        int m = idx >> 3, kq = (idx & 7) << 2; \
        int ms = m ^ kq; \
        (dst)[(kq + 0) * ASTRIDE + ms] = ra[q].x; \
        (dst)[(kq + 1) * ASTRIDE + ms] = ra[q].y; \
        (dst)[(kq + 2) * ASTRIDE + ms] = ra[q].z; \
        (dst)[(kq + 3) * ASTRIDE + ms] = ra[q].w; \
    } \
} while (0)
#define CPA_B(k0, stB) do { \
    uint32_t sb = smem_u32(smB + (stB) * BSTAGE) + (uint32_t)tid * 16u; \
    _Pragma("unroll") \
    for (int q = 0; q < 8; q++) { \
        int idx = q * 128 + tid; \
        int k = idx >> 5, c4 = (idx & 31) << 2; \
        cp_async16(sb + q * 2048u, Bb + (size_t)((k0) + k) * ldb + c4); \
    } \
    CP_COMMIT(); \
} while (0)

    // ---- prologue ----
    CPA_B(0, 0);
    LDG_A(0);
    STS_A(smA);
    CP_WAIT0();
    __syncthreads();

    for (int c = 0; c < CH; c++) {
        const int st = c & 1;
        const int nx2 = st ^ 1;
        if (c + 1 < CH) {
            CPA_B((c + 1) * GTK, nx2);
            LDG_A((c + 1) * GTK);
        }

        const float* Asm = smA + st * ASTAGE;
        const float* Bsm = smB + st * BSTAGE;
#pragma unroll
        for (int k = 0; k < GTK; k++) {
            const int sw = k & 28;
            ulonglong2 ap0 = *(const ulonglong2*)&Asm[k * ASTRIDE + ((4 * lm) ^ sw)];
            ulonglong2 ap1 = *(const ulonglong2*)&Asm[k * ASTRIDE + (32 + ((4 * lm) ^ sw))];
            float4 b0 = *(const float4*)&Bsm[k * GTN + col0];
            float4 b1 = *(const float4*)&Bsm[k * GTN + col0 + 4];
            unsigned long long bd[8];
            bd[0] = dup2(b0.x); bd[1] = dup2(b0.y); bd[2] = dup2(b0.z); bd[3] = dup2(b0.w);
            bd[4] = dup2(b1.x); bd[5] = dup2(b1.y); bd[6] = dup2(b1.z); bd[7] = dup2(b1.w);
            unsigned long long ap[4] = {ap0.x, ap0.y, ap1.x, ap1.y};
#pragma unroll
            for (int r = 0; r < 4; r++)
#pragma unroll
                for (int cc = 0; cc < 8; cc++)
                    ffma2(acc[r][cc], ap[r], bd[cc]);
        }

        if (c + 1 < CH) STS_A(smA + nx2 * ASTAGE);
        CP_WAIT0();
        __syncthreads();
    }

    // ---- epilogue ----
    const int colg = colg0 + col0;
    float bb[8] = {0, 0, 0, 0, 0, 0, 0, 0};
    if (isEnt) {
        float4 t0 = *(const float4*)(b1e + colg);
        float4 t1 = *(const float4*)(b1e + colg + 4);
        bb[0] = t0.x; bb[1] = t0.y; bb[2] = t0.z; bb[3] = t0.w;
        bb[4] = t1.x; bb[5] = t1.y; bb[6] = t1.z; bb[7] = t1.w;
    }
#pragma unroll
    for (int rp = 0; rp < 4; rp++) {
        int r0 = (rp < 2) ? (4 * lm + 2 * rp) : (32 + 4 * lm + 2 * (rp - 2));
        float lo[8], hi[8];
#pragma unroll
        for (int cc = 0; cc < 8; cc++) {
            float2 v = unpack2(acc[rp][cc]);
            lo[cc] = v.x + bb[cc];
            hi[cc] = v.y + bb[cc];
        }
        if (isEnt) {
#pragma unroll
            for (int q = 0; q < 8; q++) {
                lo[q] = fmaxf(lo[q], 0.f);
                hi[q] = fmaxf(hi[q], 0.f);
            }
        }
        float* C0 = Cb + (size_t)(bm + r0) * ldc + colg;
        float* C1 = Cb + (size_t)(bm + r0 + 1) * ldc + colg;
        *(float4*)C0 = make_float4(lo[0], lo[1], lo[2], lo[3]);
        *(float4*)(C0 + 4) = make_float4(lo[4], lo[5], lo[6], lo[7]);
        *(float4*)C1 = make_float4(hi[0], hi[1], hi[2], hi[3]);
        *(float4*)(C1 + 4) = make_float4(hi[4], hi[5], hi[6], hi[7]);
    }
#undef LDG_A
#undef STS_A
#undef CPA_B
}

// ===========================================================================
// Merged launch 3: EL | combine_transpose | pair-table | W2r padding.
// ===========================================================================
#define ELBLKS (MS / 8)                      // 1024
#define CTBLKS ((PAIRN / 32) * (ME / 32))    // 1536
#define PTBLKS 8                             // 8*256 = 2048 >= NPAIR
#define WPBLKS 36                            // 36*256 = 9216 = 768*12

__global__ __launch_bounds__(256) void el_combine_kernel(
    const float* __restrict__ W2e, const float* __restrict__ b2e,
    const float* __restrict__ b1r, const float* __restrict__ W2r,
    float* __restrict__ el_out)
{
    __shared__ float W2s[HH * ET];           // EL use (13.8 KB)
    __shared__ float t[32][33];              // combine use (4.3 KB)
    const int tid = threadIdx.x;

    if (blockIdx.x < ELBLKS) {
        // ---------------- entity logits ----------------
        for (int i = tid; i < HH * ET; i += 256) W2s[i] = W2e[i];
        __syncthreads();

        const int warp = tid >> 5, lane = tid & 31;
        const int row = blockIdx.x * 8 + warp;
        const float* hrow = g_hidden + (size_t)row * HH;

        float acc[ET];
#pragma unroll
        for (int c = 0; c < ET; c++) acc[c] = 0.f;

#pragma unroll
        for (int kk = 0; kk < HH / 32; kk++) {
            int k = kk * 32 + lane;
            float h = hrow[k];
            const float* w = &W2s[k * ET];
#pragma unroll
            for (int c = 0; c < ET; c++) acc[c] += h * w[c];
        }
#pragma unroll
        for (int c = 0; c < ET; c++)
#pragma unroll
            for (int off = 16; off > 0; off >>= 1)
                acc[c] += __shfl_down_sync(0xffffffffu, acc[c], off);

        if (lane == 0) {
            float* o = el_out + (size_t)row * ET;
#pragma unroll
            for (int c = 0; c < ET; c++) o[c] = acc[c] + b2e[c];
        }
    } else if (blockIdx.x < ELBLKS + CTBLKS) {
        // ---------------- combine + transpose ----------------
        const int cb = blockIdx.x - ELBLKS;          // 0..1535
        const int kb = (cb % (PAIRN / 32)) * 32;     // k' base
        const int eb = (cb / (PAIRN / 32)) * 32;     // entity-row base
        const int tx = tid & 31;
        const int ty = tid >> 5;                      // 0..7

#pragma unroll
        for (int s = 0; s < 4; s++) {
            int e = eb + ty + s * 8;
            size_t off = (size_t)e * PAIRN + kb + tx;
            float v = g_pK[0][off];
#pragma unroll
            for (int zz = 1; zz < ZPAIR; zz++) v += g_pK[zz][off];
            t[ty + s * 8][tx] = v;
        }
        __syncthreads();

        const int b = eb >> 6;
        const int n0 = eb & 63;
#pragma unroll
        for (int s = 0; s < 4; s++) {
            int kk = kb + ty + s * 8;
            float v = t[tx][ty + s * 8];
            if (kk < Hdim) {
                v += b1r[kk];
                g_pAT[((size_t)b * Hdim + kk) * Nent + n0 + tx] = v;
            } else {
                g_pBT[((size_t)b * Hdim + (kk - Hdim)) * Nent + n0 + tx] = v;
            }
        }
    } else if (blockIdx.x < ELBLKS + CTBLKS + PTBLKS) {
        // ---------------- pair index table ----------------
        int p = (blockIdx.x - ELBLKS - CTBLKS) * 256 + tid;
        if (p < NPAIR) {
            int rem = p, i = 0;
            while (rem >= (Nent - 1) - i) { rem -= (Nent - 1) - i; i++; }
            g_pairs[p * 2]     = i;
            g_pairs[p * 2 + 1] = i + 1 + rem;
        }
    } else {
        // ---------------- W2r padded to [768][12] ----------------
        int idx = (blockIdx.x - ELBLKS - CTBLKS - PTBLKS) * 256 + tid;
        if (idx < Hdim * 12) {
            int k = idx / 12, c = idx % 12;
            g_Wp12[idx] = (c < RT) ? W2r[k * RT + c] : 0.f;
        }
    }
}

// ===========================================================================
// Span mean pooling, fixed 16-iteration predicated loop.
// ===========================================================================
__global__ __launch_bounds__(192) void span_pool_kernel(
    const float4* __restrict__ seq4, const int* __restrict__ spans,
    float4* __restrict__ er4)
{
    const int bn = blockIdx.x;
    const int b = bn >> 6;
    const int s0 = spans[bn * 2];
    const int s1 = spans[bn * 2 + 1];
    int cnt = s1 - s0; if (cnt < 1) cnt = 1;
    const float inv = 1.f / (float)cnt;
    const float4* base = seq4 + (size_t)b * Ssz * (Hdim / 4) + threadIdx.x;

    float4 acc = make_float4(0.f, 0.f, 0.f, 0.f);
#pragma unroll
    for (int q = 0; q < 16; q++) {
        int s = s0 + q;
        float4 v = base[(size_t)s * (Hdim / 4)];
        if (s < s1) { acc.x += v.x; acc.y += v.y; acc.z += v.z; acc.w += v.w; }
    }
    acc.x *= inv; acc.y *= inv; acc.z *= inv; acc.w *= inv;
    er4[(size_t)bn * (Hdim / 4) + threadIdx.x] = acc;
}

// ===========================================================================
// relation_logits: block = 128 pairs of one batch b, k-tiled smem staging.
// All pairs in a batch share At[k][0..63] / Bt[k][0..63] (512 B per k) —
// stage KT k-rows in smem, inner loop is pure LDS + FFMA2.
// h(k) = relu(At[k][i] + Bt[k][j]);  logits = h @ W2r + b2r
// ===========================================================================
#define KT 64

__global__ __launch_bounds__(128) void relation_kernel(
    const float* __restrict__ b2r, float* __restrict__ out)
{
    __shared__ float sA[KT][Nent];           // 16 KB
    __shared__ float sB[KT][Nent];           // 16 KB
    __shared__ __align__(16) float sW[KT][12];  // 3 KB

    const int tid = threadIdx.x;
    const int b = blockIdx.y;
    const int p = blockIdx.x * 128 + tid;
    const bool act = (p < NPAIR);
    const int pc = act ? p : 0;
    const int i = g_pairs[pc * 2];
    const int j = g_pairs[pc * 2 + 1];

    const float* At = g_pAT + (size_t)b * Hdim * Nent;
    const float* Bt = g_pBT + (size_t)b * Hdim * Nent;

    unsigned long long acc[6];
#pragma unroll
    for (int c = 0; c < 6; c++) acc[c] = 0ull;

    for (int kb = 0; kb < Hdim; kb += KT) {
        __syncthreads();
        // Stage At/Bt tiles: KT*64 floats = 1024 float4 each, 8/thread
#pragma unroll
        for (int q = 0; q < 8; q++) {
            int idx = q * 128 + tid;
            int kk = idx >> 4, n4 = (idx & 15) << 2;
            *(float4*)&sA[kk][n4] = *(const float4*)(At + (size_t)(kb + kk) * Nent + n4);
            *(float4*)&sB[kk][n4] = *(const float4*)(Bt + (size_t)(kb + kk) * Nent + n4);
        }
        // Stage W tile: KT*12 floats = 192 float4, <=2/thread
#pragma unroll
        for (int q = 0; q < 2; q++) {
            int idx = q * 128 + tid;
            if (idx < KT * 3) {
                int kk = idx / 3, c4 = (idx % 3) << 2;
                *(float4*)&sW[kk][c4] =
                    *(const float4*)(g_Wp12 + (size_t)(kb + kk) * 12 + c4);
            }
        }
        __syncthreads();

#pragma unroll 4
        for (int kk = 0; kk < KT; kk++) {
            float h = fmaxf(sA[kk][i] + sB[kk][j], 0.f);
            unsigned long long hd = dup2(h);
            const ulonglong2* w = (const ulonglong2*)&sW[kk][0];
            ulonglong2 w0 = w[0], w1 = w[1], w2 = w[2];
            ffma2(acc[0], hd, w0.x); ffma2(acc[1], hd, w0.y);
            ffma2(acc[2], hd, w1.x); ffma2(acc[3], hd, w1.y);
            ffma2(acc[4], hd, w2.x); ffma2(acc[5], hd, w2.y);
        }
    }

    if (act) {
        float o[12];
#pragma unroll
        for (int c = 0; c < 6; c++) {
            float2 v = unpack2(acc[c]);
            o[c * 2] = v.x; o[c * 2 + 1] = v.y;
        }
        float* dst = out + (size_t)(b * NPAIR + p) * RT;
#pragma unroll
        for (int c = 0; c < RT; c++) dst[c] = o[c] + b2r[c];
    }
}

// ===========================================================================
extern "C" void kernel_launch(void* const* d_in, const int* in_sizes, int n_in,
                              void* d_out, int out_size)
{
    const float* seq   = (const float*)d_in[0];
    const int*   spans = (const int*)d_in[2];
    const float* W1e   = (const float*)d_in[3];
    const float* b1e   = (const float*)d_in[4];
    const float* W2e   = (const float*)d_in[5];
    const float* b2e   = (const float*)d_in[6];
    const float* W1r   = (const float*)d_in[7];
    const float* b1r   = (const float*)d_in[8];
    const float* W2r   = (const float*)d_in[9];
    const float* b2r   = (const float*)d_in[10];

    float* out = (float*)d_out;
    float* EL = out;                                   // [16,512,9]
    float* ER = out + (size_t)MS * ET;                 // [16,64,768]
    float* RL = ER + (size_t)ME * Hdim;                // [16,2016,10]

    void *p_hidden, *p_pK;
    cudaGetSymbolAddress(&p_hidden, g_hidden);
    cudaGetSymbolAddress(&p_pK, g_pK);

    cudaFuncSetAttribute(gemm_mega,
                         cudaFuncAttributeMaxDynamicSharedMemorySize, GEMM_SMEM);

    // 1) entity_repr (output + input of pair GEMM)
    span_pool_kernel<<<Bsz * Nent, 192>>>((const float4*)seq, spans, (float4*)ER);

    // 2) merged GEMMs: hidden (entity) + pK[z] (pair split-K=4), 1152 CTAs
    gemm_mega<<<1152, 128, GEMM_SMEM>>>(
        seq, W1e, b1e, (float*)p_hidden, ER, W1r, (float*)p_pK);

    // 3) entity_logits | combine+transpose | pair table | W2r pad
    el_combine_kernel<<<ELBLKS + CTBLKS + PTBLKS + WPBLKS, 256>>>(
        W2e, b2e, b1r, W2r, EL);

    // 4) relation_logits (smem-staged)
    relation_kernel<<<dim3((NPAIR + 127) / 128, Bsz), 128>>>(b2r, RL);
}